// round 14
// baseline (speedup 1.0000x reference)
#include <cuda_runtime.h>

#define B_ 4
#define T_ 2048
#define H_ 16
#define D_ 128
#define HD 2048        // H_*D_
#define S_ 16          // steps per chunk
#define NC (T_/S_)     // 128 chunks

// smem float offsets. Tiles double-buffered (parity): buffer stride 8192.
#define FS 0           // f rows:  16 t * 128
#define KS 2048        // kg rows
#define QS 4096        // q rows
#define FC 6144        // f cols: 16 t * 64
#define VG 7168        // vg cols
#define TILE_SZ 8192
#define PT 16384       // partials: 2 parity * 16 s * (16 rp * 68 = 1088)
#define PT_PAR 17408
#define SM_FLOATS (16384 + 2 * 17408)
#define SM_BYTES  (SM_FLOATS * 4)    // 204800

typedef unsigned long long u64;

__device__ __forceinline__ u64 pk2(float x, float y) {
    u64 r; asm("mov.b64 %0,{%1,%2};" : "=l"(r) : "f"(x), "f"(y)); return r;
}
__device__ __forceinline__ float2 up2(u64 a) {
    float2 r; asm("mov.b64 {%0,%1},%2;" : "=f"(r.x), "=f"(r.y) : "l"(a)); return r;
}
__device__ __forceinline__ u64 mul2(u64 a, u64 b) {
    u64 d; asm("mul.rn.f32x2 %0,%1,%2;" : "=l"(d) : "l"(a), "l"(b)); return d;
}
__device__ __forceinline__ u64 add2(u64 a, u64 b) {
    u64 d; asm("add.rn.f32x2 %0,%1,%2;" : "=l"(d) : "l"(a), "l"(b)); return d;
}
__device__ __forceinline__ u64 fma2(u64 a, u64 b, u64 c) {
    u64 d; asm("fma.rn.f32x2 %0,%1,%2,%3;" : "=l"(d) : "l"(a), "l"(b), "l"(c)); return d;
}
__device__ __forceinline__ u64 max2c(u64 a, float c) {
    float2 t = up2(a);
    t.x = fmaxf(t.x, c); t.y = fmaxf(t.y, c);
    return pk2(t.x, t.y);
}
__device__ __forceinline__ u64 shflx8(u64 x) {   // shfl_xor(8) of a packed pair
    unsigned lo, hi;
    asm("mov.b64 {%0,%1},%2;" : "=r"(lo), "=r"(hi) : "l"(x));
    lo = __shfl_xor_sync(0xffffffffu, lo, 8);
    hi = __shfl_xor_sync(0xffffffffu, hi, 8);
    u64 r; asm("mov.b64 %0,{%1,%2};" : "=l"(r) : "r"(lo), "r"(hi));
    return r;
}

// per-column piece of one step: updates 2 packed M chains, emits scalar col-partial
#define COLJ(fcj, vgj, m0, m1, ocj) {                                     \
    const u64 fj = pk2(fcj, fcj);                                         \
    const u64 vj = pk2(vgj, vgj);                                         \
    const u64 fo0 = max2c(mul2(fp0, fj), 0.8f);                           \
    const u64 fo1 = max2c(mul2(fp1, fj), 0.8f);                           \
    m0 = fma2(m0, fo0, mul2(kp0, vj));                                    \
    m1 = fma2(m1, fo1, mul2(kp1, vj));                                    \
    u64 op = mul2(qp0, m0);                                               \
    op = fma2(qp1, m1, op);                                               \
    const float2 oo = up2(op);                                            \
    ocj = oo.x + oo.y;                                                    \
}

__global__ __launch_bounds__(512, 1) void delta_kernel(
    const float* __restrict__ q, const float* __restrict__ k,
    const float* __restrict__ v, const float* __restrict__ f,
    const float* __restrict__ g, float* __restrict__ out)
{
    extern __shared__ float smp[];

    const int tid  = threadIdx.x;
    const int w    = tid >> 5, lane = tid & 31;
    const int rt   = w >> 1;            // 8 row-tiles of 16 rows
    const int ct   = w & 1;             // 2 col-tiles of 32 cols
    const int lr   = lane >> 3;         // 4 row-blocks of 4 rows
    const int lc   = lane & 7;          // 8 col-blocks of 4 cols
    const int colbase = blockIdx.x * 64;
    const long base0  = (long)blockIdx.z * T_ * HD + (long)blockIdx.y * D_;

    const int R0 = rt * 16 + lr * 4;    // my 4 rows
    const int C0 = ct * 32 + lc * 4;    // my 4 cols (local)
    const int rp68 = (rt * 2 + (lr >> 1)) * 68;   // partial row-part slot (16B aligned)
    const bool stsOK = ((lr & 1) == 0);

    // staging roles
    const int  s_s = tid >> 5, s_rb = tid & 31;   // rows: (t, 4-float granule)
    const int  c_s = tid >> 4, c_cb = tid & 15;   // cols: (t, 4-col block), tid<256
    const bool colth = (tid < 256);
    const long growb = base0 + (long)s_s * HD + s_rb * 4;
    const long gcolb = base0 + (long)c_s * HD + colbase + c_cb * 4;
    const int  rbidx = s_s * 128 + s_rb * 4;
    const int  cidx  = c_s * 64 + c_cb * 4;

    // prefetch chunk 0
    float4 pq  = *(const float4*)(q + growb);
    float4 pk_ = *(const float4*)(k + growb);
    float4 pg  = *(const float4*)(g + growb);
    float4 pf  = *(const float4*)(f + growb);
    float4 cv, cg2, cf;
    if (colth) {
        cv  = *(const float4*)(v + gcolb);
        cg2 = *(const float4*)(g + gcolb);
        cf  = *(const float4*)(f + gcolb);
    }

    // state: 4 rows x 4 cols = 8 packed f32x2 (pairs along rows)
    u64 M[8];
#pragma unroll
    for (int p = 0; p < 8; p++) M[p] = 0ull;

    for (int ch = 0; ch < NC; ch++) {
        const int par = ch & 1;
        float* tb = smp + par * TILE_SZ;
        // ---- stage prefetched regs -> parity tile buffer ----
        {
            float4 kg;
            kg.x = pk_.x * pg.x; kg.y = pk_.y * pg.y;
            kg.z = pk_.z * pg.z; kg.w = pk_.w * pg.w;
            *(float4*)(tb + FS + rbidx) = pf;
            *(float4*)(tb + KS + rbidx) = kg;
            *(float4*)(tb + QS + rbidx) = pq;
            if (colth) {
                float4 vg;
                vg.x = cv.x * cg2.x; vg.y = cv.y * cg2.y;
                vg.z = cv.z * cg2.z; vg.w = cv.w * cg2.w;
                *(float4*)(tb + VG + cidx) = vg;
                *(float4*)(tb + FC + cidx) = cf;
            }
        }
        __syncthreads();   // the ONLY barrier per chunk
        // ---- prefetch next chunk (latency overlaps compute) ----
        if (ch + 1 < NC) {
            const long off = (long)(ch + 1) * S_ * HD;
            pq  = *(const float4*)(q + growb + off);
            pk_ = *(const float4*)(k + growb + off);
            pg  = *(const float4*)(g + growb + off);
            pf  = *(const float4*)(f + growb + off);
            if (colth) {
                cv  = *(const float4*)(v + gcolb + off);
                cg2 = *(const float4*)(g + gcolb + off);
                cf  = *(const float4*)(f + gcolb + off);
            }
        }
        // ---- compute 16 steps ----
        float* pw = smp + PT + par * PT_PAR + rp68 + C0;
#pragma unroll
        for (int s = 0; s < S_; s++) {
            const ulonglong2 f2 = *(const ulonglong2*)(tb + FS + s * 128 + R0);
            const ulonglong2 k2 = *(const ulonglong2*)(tb + KS + s * 128 + R0);
            const ulonglong2 q2 = *(const ulonglong2*)(tb + QS + s * 128 + R0);
            const float4 fc4 = *(const float4*)(tb + FC + s * 64 + C0);
            const float4 vg4 = *(const float4*)(tb + VG + s * 64 + C0);
            const u64 fp0 = f2.x, fp1 = f2.y;
            const u64 kp0 = k2.x, kp1 = k2.y;
            const u64 qp0 = q2.x, qp1 = q2.y;
            float oc0, oc1, oc2, oc3;
            COLJ(fc4.x, vg4.x, M[0], M[1], oc0)
            COLJ(fc4.y, vg4.y, M[2], M[3], oc1)
            COLJ(fc4.z, vg4.z, M[4], M[5], oc2)
            COLJ(fc4.w, vg4.w, M[6], M[7], oc3)
            // one butterfly round over xor-8 partner (lr pairs 0/1 and 2/3)
            u64 oA = pk2(oc0, oc1), oB = pk2(oc2, oc3);
            oA = add2(oA, shflx8(oA));
            oB = add2(oB, shflx8(oB));
            if (stsOK) {
                const float2 A = up2(oA), Bv = up2(oB);
                *(float4*)(pw + s * 1088) = make_float4(A.x, A.y, Bv.x, Bv.y);
            }
        }
        // ---- reduce prev chunk's partials -> gmem (post-compute: MIO drained) ----
        if (ch > 0 && colth) {
            const float* pb = smp + PT + (1 - par) * PT_PAR;
            const int s2 = tid >> 4, cg = tid & 15;
            const float* p = pb + s2 * 1088 + cg * 4;
            u64 a0 = 0ull, a1 = 0ull;
#pragma unroll
            for (int rp = 0; rp < 16; rp++) {
                const float4 x = *(const float4*)(p + rp * 68);
                a0 = add2(a0, pk2(x.x, x.y));
                a1 = add2(a1, pk2(x.z, x.w));
            }
            const float2 r0 = up2(a0), r1 = up2(a1);
            *(float4*)(out + base0 + (long)(ch - 1) * S_ * HD + (long)s2 * HD
                       + colbase + cg * 4) = make_float4(r0.x, r0.y, r1.x, r1.y);
        }
    }
    // ---- drain: reduce final chunk's partials ----
    __syncthreads();
    if (colth) {
        const float* pb = smp + PT + ((NC - 1) & 1) * PT_PAR;
        const int s2 = tid >> 4, cg = tid & 15;
        const float* p = pb + s2 * 1088 + cg * 4;
        u64 a0 = 0ull, a1 = 0ull;
#pragma unroll
        for (int rp = 0; rp < 16; rp++) {
            const float4 x = *(const float4*)(p + rp * 68);
            a0 = add2(a0, pk2(x.x, x.y));
            a1 = add2(a1, pk2(x.z, x.w));
        }
        const float2 r0 = up2(a0), r1 = up2(a1);
        *(float4*)(out + base0 + (long)(NC - 1) * S_ * HD + (long)s2 * HD
                   + colbase + cg * 4) = make_float4(r0.x, r0.y, r1.x, r1.y);
    }
}

extern "C" void kernel_launch(void* const* d_in, const int* in_sizes, int n_in,
                              void* d_out, int out_size) {
    const float* q = (const float*)d_in[0];
    const float* k = (const float*)d_in[1];
    const float* v = (const float*)d_in[2];
    const float* f = (const float*)d_in[3];
    const float* g = (const float*)d_in[4];
    cudaFuncSetAttribute(delta_kernel,
                         cudaFuncAttributeMaxDynamicSharedMemorySize, SM_BYTES);
    dim3 grid(2, H_, B_);
    delta_kernel<<<grid, 512, SM_BYTES>>>(q, k, v, f, g, (float*)d_out);
}

// round 15
// speedup vs baseline: 1.0540x; 1.0540x over previous
#include <cuda_runtime.h>

#define B_ 4
#define T_ 2048
#define H_ 16
#define D_ 128
#define HD 2048        // H_*D_
#define S_ 16          // steps per chunk
#define NC (T_/S_)     // 128 chunks

// smem float offsets
#define FS 0           // f rows:  16 t * 128
#define KS 2048        // kg rows
#define QS 4096        // q rows
#define FC 6144        // f cols: 16 t * 64
#define VG 7168        // vg cols
#define PT 8192        // partials: 2 parity * 16 s * (16 rp * 68 = 1088)
#define PT_PAR 17408
#define SM_FLOATS (8192 + 2 * 17408)
#define SM_BYTES  (SM_FLOATS * 4)    // 172032

typedef unsigned long long u64;

__device__ __forceinline__ u64 pk2(float x, float y) {
    u64 r; asm("mov.b64 %0,{%1,%2};" : "=l"(r) : "f"(x), "f"(y)); return r;
}
__device__ __forceinline__ float2 up2(u64 a) {
    float2 r; asm("mov.b64 {%0,%1},%2;" : "=f"(r.x), "=f"(r.y) : "l"(a)); return r;
}
__device__ __forceinline__ u64 mul2(u64 a, u64 b) {
    u64 d; asm("mul.rn.f32x2 %0,%1,%2;" : "=l"(d) : "l"(a), "l"(b)); return d;
}
__device__ __forceinline__ u64 add2(u64 a, u64 b) {
    u64 d; asm("add.rn.f32x2 %0,%1,%2;" : "=l"(d) : "l"(a), "l"(b)); return d;
}
__device__ __forceinline__ u64 fma2(u64 a, u64 b, u64 c) {
    u64 d; asm("fma.rn.f32x2 %0,%1,%2,%3;" : "=l"(d) : "l"(a), "l"(b), "l"(c)); return d;
}
__device__ __forceinline__ u64 max2c(u64 a, float c) {
    float2 t = up2(a);
    t.x = fmaxf(t.x, c); t.y = fmaxf(t.y, c);
    return pk2(t.x, t.y);
}
__device__ __forceinline__ u64 shflx8(u64 x) {   // shfl_xor(8) of a packed pair
    unsigned lo, hi;
    asm("mov.b64 {%0,%1},%2;" : "=r"(lo), "=r"(hi) : "l"(x));
    lo = __shfl_xor_sync(0xffffffffu, lo, 8);
    hi = __shfl_xor_sync(0xffffffffu, hi, 8);
    u64 r; asm("mov.b64 %0,{%1,%2};" : "=l"(r) : "r"(lo), "r"(hi));
    return r;
}

// per-column piece of one step: updates 2 packed M chains, emits scalar col-partial
#define COLJ(fcj, vgj, m0, m1, ocj) {                                     \
    const u64 fj = pk2(fcj, fcj);                                         \
    const u64 vj = pk2(vgj, vgj);                                         \
    const u64 fo0 = max2c(mul2(fp0, fj), 0.8f);                           \
    const u64 fo1 = max2c(mul2(fp1, fj), 0.8f);                           \
    m0 = fma2(m0, fo0, mul2(kp0, vj));                                    \
    m1 = fma2(m1, fo1, mul2(kp1, vj));                                    \
    u64 op = mul2(qp0, m0);                                               \
    op = fma2(qp1, m1, op);                                               \
    const float2 oo = up2(op);                                            \
    ocj = oo.x + oo.y;                                                    \
}

__global__ __launch_bounds__(512, 1) void delta_kernel(
    const float* __restrict__ q, const float* __restrict__ k,
    const float* __restrict__ v, const float* __restrict__ f,
    const float* __restrict__ g, float* __restrict__ out)
{
    extern __shared__ float smp[];

    const int tid  = threadIdx.x;
    const int w    = tid >> 5, lane = tid & 31;
    const int rt   = w >> 1;            // 8 row-tiles of 16 rows
    const int ct   = w & 1;             // 2 col-tiles of 32 cols
    const int lr   = lane >> 3;         // 4 row-blocks of 4 rows
    const int lc   = lane & 7;          // 8 col-blocks of 4 cols
    const int colbase = blockIdx.x * 64;
    const long base0  = (long)blockIdx.z * T_ * HD + (long)blockIdx.y * D_;

    const int R0 = rt * 16 + lr * 4;    // my 4 rows
    const int C0 = ct * 32 + lc * 4;    // my 4 cols (local)
    const int rp68 = (rt * 2 + (lr >> 1)) * 68;   // partial row-part slot (16B aligned)
    const bool stsOK = ((lr & 1) == 0);

    // staging roles
    const int  s_s = tid >> 5, s_rb = tid & 31;   // rows: (t, 4-float granule)
    const int  c_s = tid >> 4, c_cb = tid & 15;   // cols: (t, 4-col block), tid<256
    const bool colth = (tid < 256);
    const long growb = base0 + (long)s_s * HD + s_rb * 4;
    const long gcolb = base0 + (long)c_s * HD + colbase + c_cb * 4;
    const int  rbidx = s_s * 128 + s_rb * 4;
    const int  cidx  = c_s * 64 + c_cb * 4;

    // prefetch chunk 0
    float4 pq  = *(const float4*)(q + growb);
    float4 pk_ = *(const float4*)(k + growb);
    float4 pg  = *(const float4*)(g + growb);
    float4 pf  = *(const float4*)(f + growb);
    float4 cv, cg2, cf;
    if (colth) {
        cv  = *(const float4*)(v + gcolb);
        cg2 = *(const float4*)(g + gcolb);
        cf  = *(const float4*)(f + gcolb);
    }

    // state: 4 rows x 4 cols = 8 packed f32x2 (pairs along rows)
    u64 M[8];
#pragma unroll
    for (int p = 0; p < 8; p++) M[p] = 0ull;

    for (int ch = 0; ch < NC; ch++) {
        const int par = ch & 1;
        __syncthreads();   // prev compute done: tiles free, partials[1-par] complete
        // ---- reduce prev chunk's partials -> gmem (overlaps staging) ----
        if (ch > 0 && colth) {
            const float* pb = smp + PT + (1 - par) * PT_PAR;
            const int s2 = tid >> 4, cg = tid & 15;
            const float* p = pb + s2 * 1088 + cg * 4;
            u64 a0 = 0ull, a1 = 0ull;
#pragma unroll
            for (int rp = 0; rp < 16; rp++) {
                const float4 x = *(const float4*)(p + rp * 68);
                a0 = add2(a0, pk2(x.x, x.y));
                a1 = add2(a1, pk2(x.z, x.w));
            }
            const float2 r0 = up2(a0), r1 = up2(a1);
            *(float4*)(out + base0 + (long)(ch - 1) * S_ * HD + (long)s2 * HD
                       + colbase + cg * 4) = make_float4(r0.x, r0.y, r1.x, r1.y);
        }
        // ---- stage prefetched regs -> smem tiles ----
        {
            float4 kg;
            kg.x = pk_.x * pg.x; kg.y = pk_.y * pg.y;
            kg.z = pk_.z * pg.z; kg.w = pk_.w * pg.w;
            *(float4*)(smp + FS + rbidx) = pf;
            *(float4*)(smp + KS + rbidx) = kg;
            *(float4*)(smp + QS + rbidx) = pq;
            if (colth) {
                float4 vg;
                vg.x = cv.x * cg2.x; vg.y = cv.y * cg2.y;
                vg.z = cv.z * cg2.z; vg.w = cv.w * cg2.w;
                *(float4*)(smp + VG + cidx) = vg;
                *(float4*)(smp + FC + cidx) = cf;
            }
        }
        __syncthreads();
        // ---- prefetch next chunk (latency overlaps compute) ----
        if (ch + 1 < NC) {
            const long off = (long)(ch + 1) * S_ * HD;
            pq  = *(const float4*)(q + growb + off);
            pk_ = *(const float4*)(k + growb + off);
            pg  = *(const float4*)(g + growb + off);
            pf  = *(const float4*)(f + growb + off);
            if (colth) {
                cv  = *(const float4*)(v + gcolb + off);
                cg2 = *(const float4*)(g + gcolb + off);
                cf  = *(const float4*)(f + gcolb + off);
            }
        }
        // ---- compute 16 steps; fc/vg software-pipelined one step ahead ----
        float* pw = smp + PT + par * PT_PAR + rp68 + C0;
        float4 fc4 = *(const float4*)(smp + FC + C0);
        float4 vg4 = *(const float4*)(smp + VG + C0);
#pragma unroll
        for (int s = 0; s < S_; s++) {
            float4 fc_n, vg_n;
            if (s + 1 < S_) {
                fc_n = *(const float4*)(smp + FC + (s + 1) * 64 + C0);
                vg_n = *(const float4*)(smp + VG + (s + 1) * 64 + C0);
            }
            const ulonglong2 f2 = *(const ulonglong2*)(smp + FS + s * 128 + R0);
            const ulonglong2 k2 = *(const ulonglong2*)(smp + KS + s * 128 + R0);
            const ulonglong2 q2 = *(const ulonglong2*)(smp + QS + s * 128 + R0);
            const u64 fp0 = f2.x, fp1 = f2.y;
            const u64 kp0 = k2.x, kp1 = k2.y;
            const u64 qp0 = q2.x, qp1 = q2.y;
            float oc0, oc1, oc2, oc3;
            COLJ(fc4.x, vg4.x, M[0], M[1], oc0)
            COLJ(fc4.y, vg4.y, M[2], M[3], oc1)
            COLJ(fc4.z, vg4.z, M[4], M[5], oc2)
            COLJ(fc4.w, vg4.w, M[6], M[7], oc3)
            // one butterfly round over xor-8 partner (lr pairs 0/1 and 2/3)
            u64 oA = pk2(oc0, oc1), oB = pk2(oc2, oc3);
            oA = add2(oA, shflx8(oA));
            oB = add2(oB, shflx8(oB));
            if (stsOK) {
                const float2 A = up2(oA), Bv = up2(oB);
                *(float4*)(pw + s * 1088) = make_float4(A.x, A.y, Bv.x, Bv.y);
            }
            if (s + 1 < S_) { fc4 = fc_n; vg4 = vg_n; }
        }
    }
    // ---- drain: reduce final chunk's partials ----
    __syncthreads();
    if (colth) {
        const float* pb = smp + PT + ((NC - 1) & 1) * PT_PAR;
        const int s2 = tid >> 4, cg = tid & 15;
        const float* p = pb + s2 * 1088 + cg * 4;
        u64 a0 = 0ull, a1 = 0ull;
#pragma unroll
        for (int rp = 0; rp < 16; rp++) {
            const float4 x = *(const float4*)(p + rp * 68);
            a0 = add2(a0, pk2(x.x, x.y));
            a1 = add2(a1, pk2(x.z, x.w));
        }
        const float2 r0 = up2(a0), r1 = up2(a1);
        *(float4*)(out + base0 + (long)(NC - 1) * S_ * HD + (long)s2 * HD
                   + colbase + cg * 4) = make_float4(r0.x, r0.y, r1.x, r1.y);
    }
}

extern "C" void kernel_launch(void* const* d_in, const int* in_sizes, int n_in,
                              void* d_out, int out_size) {
    const float* q = (const float*)d_in[0];
    const float* k = (const float*)d_in[1];
    const float* v = (const float*)d_in[2];
    const float* f = (const float*)d_in[3];
    const float* g = (const float*)d_in[4];
    cudaFuncSetAttribute(delta_kernel,
                         cudaFuncAttributeMaxDynamicSharedMemorySize, SM_BYTES);
    dim3 grid(2, H_, B_);
    delta_kernel<<<grid, 512, SM_BYTES>>>(q, k, v, f, g, (float*)d_out);
}

// round 16
// speedup vs baseline: 1.0921x; 1.0361x over previous
#include <cuda_runtime.h>

#define B_ 4
#define T_ 2048
#define H_ 16
#define D_ 128
#define HD 2048        // H_*D_
#define S_ 16          // steps per chunk
#define NC (T_/S_)     // 128 chunks

// smem float offsets (FC tile removed: fc comes from the FS row tile)
#define FS 0           // f rows:  16 t * 128  (covers ALL 128 d -> also column f)
#define KS 2048        // kg rows
#define QS 4096        // q rows
#define VG 6144        // vg cols: 16 t * 64
#define PT 7168        // partials: 2 parity * 16 s * (16 rp * 68 = 1088)
#define PT_PAR 17408
#define SM_FLOATS (7168 + 2 * 17408)
#define SM_BYTES  (SM_FLOATS * 4)    // 167936

typedef unsigned long long u64;

__device__ __forceinline__ u64 pk2(float x, float y) {
    u64 r; asm("mov.b64 %0,{%1,%2};" : "=l"(r) : "f"(x), "f"(y)); return r;
}
__device__ __forceinline__ float2 up2(u64 a) {
    float2 r; asm("mov.b64 {%0,%1},%2;" : "=f"(r.x), "=f"(r.y) : "l"(a)); return r;
}
__device__ __forceinline__ u64 mul2(u64 a, u64 b) {
    u64 d; asm("mul.rn.f32x2 %0,%1,%2;" : "=l"(d) : "l"(a), "l"(b)); return d;
}
__device__ __forceinline__ u64 add2(u64 a, u64 b) {
    u64 d; asm("add.rn.f32x2 %0,%1,%2;" : "=l"(d) : "l"(a), "l"(b)); return d;
}
__device__ __forceinline__ u64 fma2(u64 a, u64 b, u64 c) {
    u64 d; asm("fma.rn.f32x2 %0,%1,%2,%3;" : "=l"(d) : "l"(a), "l"(b), "l"(c)); return d;
}
__device__ __forceinline__ u64 max2c(u64 a, float c) {
    float2 t = up2(a);
    t.x = fmaxf(t.x, c); t.y = fmaxf(t.y, c);
    return pk2(t.x, t.y);
}
__device__ __forceinline__ u64 shflx8(u64 x) {   // shfl_xor(8) of a packed pair
    unsigned lo, hi;
    asm("mov.b64 {%0,%1},%2;" : "=r"(lo), "=r"(hi) : "l"(x));
    lo = __shfl_xor_sync(0xffffffffu, lo, 8);
    hi = __shfl_xor_sync(0xffffffffu, hi, 8);
    u64 r; asm("mov.b64 %0,{%1,%2};" : "=l"(r) : "r"(lo), "r"(hi));
    return r;
}

// per-column piece of one step: updates 2 packed M chains, emits scalar col-partial
#define COLJ(fcj, vgj, m0, m1, ocj) {                                     \
    const u64 fj = pk2(fcj, fcj);                                         \
    const u64 vj = pk2(vgj, vgj);                                         \
    const u64 fo0 = max2c(mul2(fp0, fj), 0.8f);                           \
    const u64 fo1 = max2c(mul2(fp1, fj), 0.8f);                           \
    m0 = fma2(m0, fo0, mul2(kp0, vj));                                    \
    m1 = fma2(m1, fo1, mul2(kp1, vj));                                    \
    u64 op = mul2(qp0, m0);                                               \
    op = fma2(qp1, m1, op);                                               \
    const float2 oo = up2(op);                                            \
    ocj = oo.x + oo.y;                                                    \
}

__global__ __launch_bounds__(512, 1) void delta_kernel(
    const float* __restrict__ q, const float* __restrict__ k,
    const float* __restrict__ v, const float* __restrict__ f,
    const float* __restrict__ g, float* __restrict__ out)
{
    extern __shared__ float smp[];

    const int tid  = threadIdx.x;
    const int w    = tid >> 5, lane = tid & 31;
    const int rt   = w >> 1;            // 8 row-tiles of 16 rows
    const int ct   = w & 1;             // 2 col-tiles of 32 cols
    const int lr   = lane >> 3;         // 4 row-blocks of 4 rows
    const int lc   = lane & 7;          // 8 col-blocks of 4 cols
    const int colbase = blockIdx.x * 64;
    const long base0  = (long)blockIdx.z * T_ * HD + (long)blockIdx.y * D_;

    const int R0 = rt * 16 + lr * 4;    // my 4 rows
    const int C0 = ct * 32 + lc * 4;    // my 4 cols (local)
    const int FCI = colbase + C0;       // column f lives in the FS row tile
    const int rp68 = (rt * 2 + (lr >> 1)) * 68;   // partial row-part slot (16B aligned)
    const bool stsOK = ((lr & 1) == 0);

    // staging roles
    const int  s_s = tid >> 5, s_rb = tid & 31;   // rows: (t, 4-float granule)
    const int  c_s = tid >> 4, c_cb = tid & 15;   // cols: (t, 4-col block), tid<256
    const bool colth = (tid < 256);
    const long growb = base0 + (long)s_s * HD + s_rb * 4;
    const long gcolb = base0 + (long)c_s * HD + colbase + c_cb * 4;
    const int  rbidx = s_s * 128 + s_rb * 4;
    const int  cidx  = c_s * 64 + c_cb * 4;

    // prefetch chunk 0 (no column-f load: FS row tile covers it)
    float4 pq  = *(const float4*)(q + growb);
    float4 pk_ = *(const float4*)(k + growb);
    float4 pg  = *(const float4*)(g + growb);
    float4 pf  = *(const float4*)(f + growb);
    float4 cv, cg2;
    if (colth) {
        cv  = *(const float4*)(v + gcolb);
        cg2 = *(const float4*)(g + gcolb);
    }

    // state: 4 rows x 4 cols = 8 packed f32x2 (pairs along rows)
    u64 M[8];
#pragma unroll
    for (int p = 0; p < 8; p++) M[p] = 0ull;

    for (int ch = 0; ch < NC; ch++) {
        const int par = ch & 1;
        __syncthreads();   // prev compute done: tiles free, partials[1-par] complete
        // ---- reduce prev chunk's partials -> gmem (overlaps staging) ----
        if (ch > 0 && colth) {
            const float* pb = smp + PT + (1 - par) * PT_PAR;
            const int s2 = tid >> 4, cg = tid & 15;
            const float* p = pb + s2 * 1088 + cg * 4;
            u64 a0 = 0ull, a1 = 0ull, a2 = 0ull, a3 = 0ull;
#pragma unroll
            for (int rp = 0; rp < 16; rp += 2) {
                const float4 x = *(const float4*)(p + rp * 68);
                const float4 y = *(const float4*)(p + (rp + 1) * 68);
                a0 = add2(a0, pk2(x.x, x.y));
                a1 = add2(a1, pk2(x.z, x.w));
                a2 = add2(a2, pk2(y.x, y.y));
                a3 = add2(a3, pk2(y.z, y.w));
            }
            const float2 r0 = up2(add2(a0, a2)), r1 = up2(add2(a1, a3));
            *(float4*)(out + base0 + (long)(ch - 1) * S_ * HD + (long)s2 * HD
                       + colbase + cg * 4) = make_float4(r0.x, r0.y, r1.x, r1.y);
        }
        // ---- stage prefetched regs -> smem tiles ----
        {
            float4 kg;
            kg.x = pk_.x * pg.x; kg.y = pk_.y * pg.y;
            kg.z = pk_.z * pg.z; kg.w = pk_.w * pg.w;
            *(float4*)(smp + FS + rbidx) = pf;
            *(float4*)(smp + KS + rbidx) = kg;
            *(float4*)(smp + QS + rbidx) = pq;
            if (colth) {
                float4 vg;
                vg.x = cv.x * cg2.x; vg.y = cv.y * cg2.y;
                vg.z = cv.z * cg2.z; vg.w = cv.w * cg2.w;
                *(float4*)(smp + VG + cidx) = vg;
            }
        }
        __syncthreads();
        // ---- prefetch next chunk (latency overlaps compute) ----
        if (ch + 1 < NC) {
            const long off = (long)(ch + 1) * S_ * HD;
            pq  = *(const float4*)(q + growb + off);
            pk_ = *(const float4*)(k + growb + off);
            pg  = *(const float4*)(g + growb + off);
            pf  = *(const float4*)(f + growb + off);
            if (colth) {
                cv  = *(const float4*)(v + gcolb + off);
                cg2 = *(const float4*)(g + gcolb + off);
            }
        }
        // ---- compute 16 steps ----
        float* pw = smp + PT + par * PT_PAR + rp68 + C0;
#pragma unroll
        for (int s = 0; s < S_; s++) {
            const ulonglong2 f2 = *(const ulonglong2*)(smp + FS + s * 128 + R0);
            const ulonglong2 k2 = *(const ulonglong2*)(smp + KS + s * 128 + R0);
            const ulonglong2 q2 = *(const ulonglong2*)(smp + QS + s * 128 + R0);
            const float4 fc4 = *(const float4*)(smp + FS + s * 128 + FCI);
            const float4 vg4 = *(const float4*)(smp + VG + s * 64 + C0);
            const u64 fp0 = f2.x, fp1 = f2.y;
            const u64 kp0 = k2.x, kp1 = k2.y;
            const u64 qp0 = q2.x, qp1 = q2.y;
            float oc0, oc1, oc2, oc3;
            COLJ(fc4.x, vg4.x, M[0], M[1], oc0)
            COLJ(fc4.y, vg4.y, M[2], M[3], oc1)
            COLJ(fc4.z, vg4.z, M[4], M[5], oc2)
            COLJ(fc4.w, vg4.w, M[6], M[7], oc3)
            // one butterfly round over xor-8 partner (lr pairs 0/1 and 2/3)
            u64 oA = pk2(oc0, oc1), oB = pk2(oc2, oc3);
            oA = add2(oA, shflx8(oA));
            oB = add2(oB, shflx8(oB));
            if (stsOK) {
                const float2 A = up2(oA), Bv = up2(oB);
                *(float4*)(pw + s * 1088) = make_float4(A.x, A.y, Bv.x, Bv.y);
            }
        }
    }
    // ---- drain: reduce final chunk's partials ----
    __syncthreads();
    if (colth) {
        const float* pb = smp + PT + ((NC - 1) & 1) * PT_PAR;
        const int s2 = tid >> 4, cg = tid & 15;
        const float* p = pb + s2 * 1088 + cg * 4;
        u64 a0 = 0ull, a1 = 0ull, a2 = 0ull, a3 = 0ull;
#pragma unroll
        for (int rp = 0; rp < 16; rp += 2) {
            const float4 x = *(const float4*)(p + rp * 68);
            const float4 y = *(const float4*)(p + (rp + 1) * 68);
            a0 = add2(a0, pk2(x.x, x.y));
            a1 = add2(a1, pk2(x.z, x.w));
            a2 = add2(a2, pk2(y.x, y.y));
            a3 = add2(a3, pk2(y.z, y.w));
        }
        const float2 r0 = up2(add2(a0, a2)), r1 = up2(add2(a1, a3));
        *(float4*)(out + base0 + (long)(NC - 1) * S_ * HD + (long)s2 * HD
                   + colbase + cg * 4) = make_float4(r0.x, r0.y, r1.x, r1.y);
    }
}

extern "C" void kernel_launch(void* const* d_in, const int* in_sizes, int n_in,
                              void* d_out, int out_size) {
    const float* q = (const float*)d_in[0];
    const float* k = (const float*)d_in[1];
    const float* v = (const float*)d_in[2];
    const float* f = (const float*)d_in[3];
    const float* g = (const float*)d_in[4];
    cudaFuncSetAttribute(delta_kernel,
                         cudaFuncAttributeMaxDynamicSharedMemorySize, SM_BYTES);
    dim3 grid(2, H_, B_);
    delta_kernel<<<grid, 512, SM_BYTES>>>(q, k, v, f, g, (float*)d_out);
}